// round 13
// baseline (speedup 1.0000x reference)
#include <cuda_runtime.h>
#include <math.h>

// ROI max pooling, two-pass, separable max decomposition:
//   Pass 1: NCHW [2,256,38,38] -> NHWC scratch [2,38,38,256]; block (0,0,0)
//           also precomputes per-roi bin bounds into packed __device__ arrays.
//   Pass 2: grid = (roi, i), 448 threads.
//     Stage 1: vertical max of strip rows [hstart,hend) over the full roi
//              column range [x1, x1+rw) into smem vmax[w][c4] (float4).
//              Two interleaved independent chains per thread (MLP 2, no
//              conditional loads - invalid second item aliases the first).
//     Stage 2: per (j, c4-lane): horizontal max over nw smem entries.
//     Epilogue: stage results in smem, write out coalesced (as R7).
//
// Bin math (non-negative ints == Python floor-div):
//   x1=floor(rx1/16),..., rh=y2-y1+1, rw=x2-x1+1
//   hstart_i = y1 + (i*rh)/7, hend_i = y1 + ((i+1)*rh+6)/7  (same for w/j)
// Coords in [0,607.9] => windows inside [0,38), non-empty; rw,rh in [1,38].

#define N_IMG 2
#define CHN   256
#define C4    (CHN/4)            // 64
#define H_    38
#define W_    38
#define HW    (H_ * W_)
#define NUM_ROIS 256
#define OUT_H 7
#define OUT_W 7
#define BINS  (OUT_H * OUT_W)
#define SPATIAL_SCALE 0.0625f
#define PTHREADS (C4 * OUT_W)    // 448

__device__ float g_featT[N_IMG * HW * CHN];     // [N][H][W][C]
__device__ int   g_base4[NUM_ROIS];             // b * HW * C4 (float4 units)
__device__ int   g_hb[NUM_ROIS * OUT_H];        // hstart | hend<<8
__device__ int   g_wb[NUM_ROIS * OUT_W];        // wstart | wend<<8

// ---------------------------------------------------------------------------
__global__ void transpose_kernel(const float* __restrict__ in,
                                 const float* __restrict__ rois)
{
    __shared__ float tile[32][33];
    int n   = blockIdx.z;
    int hw0 = blockIdx.x * 32;
    int c0  = blockIdx.y * 32;

    if (blockIdx.x == 0 && blockIdx.y == 0 && blockIdx.z == 0) {
        int t = threadIdx.y * 32 + threadIdx.x;     // 0..255
        if (t < NUM_ROIS) {
            const float* r = rois + t * 5;
            int b  = (int)r[0];
            int x1 = (int)floorf(r[1] * SPATIAL_SCALE);
            int y1 = (int)floorf(r[2] * SPATIAL_SCALE);
            int x2 = (int)floorf(r[3] * SPATIAL_SCALE);
            int y2 = (int)floorf(r[4] * SPATIAL_SCALE);
            int rh = y2 - y1 + 1;
            int rw = x2 - x1 + 1;
            g_base4[t] = b * HW * C4;
            #pragma unroll
            for (int i = 0; i < OUT_H; ++i) {
                int hs = y1 + (i * rh) / OUT_H;
                int he = y1 + ((i + 1) * rh + OUT_H - 1) / OUT_H;
                g_hb[t * OUT_H + i] = hs | (he << 8);
            }
            #pragma unroll
            for (int j = 0; j < OUT_W; ++j) {
                int ws = x1 + (j * rw) / OUT_W;
                int we = x1 + ((j + 1) * rw + OUT_W - 1) / OUT_W;
                g_wb[t * OUT_W + j] = ws | (we << 8);
            }
        }
    }

    const float* inp  = in      + (size_t)n * CHN * HW;
    float*       outp = g_featT + (size_t)n * HW * CHN;

    #pragma unroll
    for (int k = 0; k < 32; k += 8) {
        int c  = c0 + threadIdx.y + k;
        int hw = hw0 + threadIdx.x;
        tile[threadIdx.y + k][threadIdx.x] =
            (hw < HW) ? inp[(size_t)c * HW + hw] : 0.0f;
    }
    __syncthreads();
    #pragma unroll
    for (int k = 0; k < 32; k += 8) {
        int hw = hw0 + threadIdx.y + k;
        if (hw < HW)
            outp[(size_t)hw * CHN + c0 + threadIdx.x] =
                tile[threadIdx.x][threadIdx.y + k];
    }
}

__device__ __forceinline__ float4 max4(float4 a, float4 b)
{
    return make_float4(fmaxf(a.x, b.x), fmaxf(a.y, b.y),
                       fmaxf(a.z, b.z), fmaxf(a.w, b.w));
}

// ---------------------------------------------------------------------------
// Pass 2: grid = (NUM_ROIS, OUT_H), block = (C4, OUT_W) = (64, 7)
// ---------------------------------------------------------------------------
__global__ void __launch_bounds__(PTHREADS, 4)
roi_pool_sep(float* __restrict__ out)
{
    __shared__ float4 vmax[W_ * C4];      // [w][c4], w relative to x1 (38KB)
    __shared__ float  s[CHN * OUT_W];     // s[c*7 + j]  (7KB)

    int roi  = blockIdx.x;
    int i    = blockIdx.y;
    int lane = threadIdx.x;               // c4 index
    int j    = threadIdx.y;
    int tid  = j * C4 + lane;             // 0..447

    int hb = g_hb[roi * OUT_H + i];
    int hstart = hb & 0xff;
    int nh = (hb >> 8) - hstart;          // 1..7, block-uniform

    int wb0 = g_wb[roi * OUT_W + 0];
    int wb6 = g_wb[roi * OUT_W + 6];
    int x1  = wb0 & 0xff;
    int rw  = (wb6 >> 8) - x1;            // 1..38, block-uniform

    const float4* gbase = (const float4*)g_featT + g_base4[roi]
                        + (size_t)(hstart * W_ + x1) * C4;

    // ---- Stage 1: vertical max into smem, 2 interleaved chains ----
    int total = rw * C4;
    for (int it = tid; it < total; it += 2 * PTHREADS) {
        int itB = it + PTHREADS;
        bool vB = (itB < total);
        const float4* pA = gbase + it;          // (w*C4 + c4) == flat index
        const float4* pB = vB ? (gbase + itB) : pA;   // alias when invalid
        float4 a = pA[0];
        float4 b = pB[0];
        for (int h = 1; h < nh; ++h) {
            a = max4(a, pA[h * (W_ * C4)]);
            b = max4(b, pB[h * (W_ * C4)]);
        }
        vmax[it] = a;
        if (vB) vmax[itB] = b;
    }
    __syncthreads();

    // ---- Stage 2: horizontal max over smem (warp-uniform bounds) ----
    int wb = g_wb[roi * OUT_W + j];
    int ws = (wb & 0xff) - x1;
    int we = (wb >> 8) - x1;

    float4 m = vmax[ws * C4 + lane];
    for (int w = ws + 1; w < we; ++w)
        m = max4(m, vmax[w * C4 + lane]);
    __syncthreads();                       // vmax reads done before s reuse? (separate arrays; sync for s write order below)

    // ---- Epilogue: stage as s[c*7 + j], then coalesced writeout ----
    int c0 = lane * 4;
    s[(c0 + 0) * OUT_W + j] = m.x;
    s[(c0 + 1) * OUT_W + j] = m.y;
    s[(c0 + 2) * OUT_W + j] = m.z;
    s[(c0 + 3) * OUT_W + j] = m.w;
    __syncthreads();

    int cq = tid / OUT_W;
    int jr = tid - cq * OUT_W;
    float* ob = out + (size_t)roi * CHN * BINS + i * OUT_W + jr;
    #pragma unroll
    for (int k = 0; k < 4; ++k)
        ob[(size_t)(cq + 64 * k) * BINS] = s[tid + k * PTHREADS];
}

extern "C" void kernel_launch(void* const* d_in, const int* in_sizes, int n_in,
                              void* d_out, int out_size)
{
    const float* feat = (const float*)d_in[0];
    const float* rois = (const float*)d_in[1];
    float* out = (float*)d_out;

    dim3 tgrid((HW + 31) / 32, CHN / 32, N_IMG);
    dim3 tblock(32, 8);
    transpose_kernel<<<tgrid, tblock>>>(feat, rois);

    dim3 pgrid(NUM_ROIS, OUT_H);
    dim3 pblock(C4, OUT_W);
    roi_pool_sep<<<pgrid, pblock>>>(out);
}

// round 14
// speedup vs baseline: 1.3727x; 1.3727x over previous
#include <cuda_runtime.h>
#include <math.h>

// ROI max pooling via 2x2 max-pyramid tables.
//
// Pass 1 (fused): NCHW [2,256,38,38] -> four NHWC tables [2,38,38,256]:
//   T00 = feat
//   TP[h][w]  = max(feat[h][w], feat[h+1][w])      (h clamped at 37)
//   TQ[h][w]  = max(feat[h][w], feat[h][w+1])      (w clamped at 37)
//   TPQ[h][w] = max of the 2x2 block               (both clamped)
//   Block (0,0,0) also precomputes per-roi bin bounds (packed ints).
//
// Pass 2: grid=(roi,i), block=(64 c4-lanes, 7 j)=448 threads; thread = one
//   bin x 4 channels. A bin [hs,he)x[ws,we) is covered by
//   ceil(nh/2) x ceil(nw/2) loads from the table matching (nh>1, nw>1),
//   at positions min(start+2k, end-2). Overlapping pairs are fine for max;
//   n==1 dims use the single-element table so nothing out of range is read.
//   Table + trip counts warp-uniform -> zero divergence. Avg ~2.4 loads/thread.
//
// Bin math (non-negative ints == Python floor-div):
//   x1=floor(rx1/16),..., rh=y2-y1+1, rw=x2-x1+1
//   hstart_i = y1 + (i*rh)/7, hend_i = y1 + ((i+1)*rh+6)/7  (same for w/j)
// Coords in [0,607.9] => windows inside [0,38), non-empty.

#define N_IMG 2
#define CHN   256
#define C4    (CHN/4)            // 64
#define H_    38
#define W_    38
#define HW    (H_ * W_)
#define NUM_ROIS 256
#define OUT_H 7
#define OUT_W 7
#define BINS  (OUT_H * OUT_W)
#define SPATIAL_SCALE 0.0625f
#define PTHREADS (C4 * OUT_W)    // 448

__device__ float g_T00[N_IMG * HW * CHN];   // [N][H][W][C]
__device__ float g_TP [N_IMG * HW * CHN];
__device__ float g_TQ [N_IMG * HW * CHN];
__device__ float g_TPQ[N_IMG * HW * CHN];
__device__ int   g_base4[NUM_ROIS];         // b * HW * C4 (float4 units)
__device__ int   g_hb[NUM_ROIS * OUT_H];    // hstart | hend<<8
__device__ int   g_wb[NUM_ROIS * OUT_W];    // wstart | wend<<8

// ---------------------------------------------------------------------------
// Pass 1: transpose + pyramid build + (block 0) bounds precompute.
// ---------------------------------------------------------------------------
__global__ void build_kernel(const float* __restrict__ in,
                             const float* __restrict__ rois)
{
    __shared__ float t00[32][33], tP[32][33], tQ[32][33], tPQ[32][33];
    int n   = blockIdx.z;
    int hw0 = blockIdx.x * 32;
    int c0  = blockIdx.y * 32;

    if (blockIdx.x == 0 && blockIdx.y == 0 && blockIdx.z == 0) {
        int t = threadIdx.y * 32 + threadIdx.x;     // 0..255
        if (t < NUM_ROIS) {
            const float* r = rois + t * 5;
            int b  = (int)r[0];
            int x1 = (int)floorf(r[1] * SPATIAL_SCALE);
            int y1 = (int)floorf(r[2] * SPATIAL_SCALE);
            int x2 = (int)floorf(r[3] * SPATIAL_SCALE);
            int y2 = (int)floorf(r[4] * SPATIAL_SCALE);
            int rh = y2 - y1 + 1;
            int rw = x2 - x1 + 1;
            g_base4[t] = b * HW * C4;
            #pragma unroll
            for (int i = 0; i < OUT_H; ++i) {
                int hs = y1 + (i * rh) / OUT_H;
                int he = y1 + ((i + 1) * rh + OUT_H - 1) / OUT_H;
                g_hb[t * OUT_H + i] = hs | (he << 8);
            }
            #pragma unroll
            for (int j = 0; j < OUT_W; ++j) {
                int ws = x1 + (j * rw) / OUT_W;
                int we = x1 + ((j + 1) * rw + OUT_W - 1) / OUT_W;
                g_wb[t * OUT_W + j] = ws | (we << 8);
            }
        }
    }

    const float* inp = in + (size_t)n * CHN * HW;
    size_t obase = (size_t)n * HW * CHN;

    #pragma unroll
    for (int k = 0; k < 32; k += 8) {
        int c  = c0 + threadIdx.y + k;
        int hw = hw0 + threadIdx.x;
        float v0 = 0.f, vh = 0.f, vw = 0.f, vhw = 0.f;
        if (hw < HW) {
            int h = hw / W_;
            int w = hw - h * W_;
            int dw = (w + 1 < W_) ? 1  : 0;
            int dh = (h + 1 < H_) ? W_ : 0;
            const float* p = inp + (size_t)c * HW + hw;
            v0  = p[0];
            vw  = p[dw];
            vh  = p[dh];
            vhw = p[dh + dw];
        }
        t00[threadIdx.y + k][threadIdx.x] = v0;
        tP [threadIdx.y + k][threadIdx.x] = fmaxf(v0, vh);
        tQ [threadIdx.y + k][threadIdx.x] = fmaxf(v0, vw);
        tPQ[threadIdx.y + k][threadIdx.x] = fmaxf(fmaxf(v0, vh), fmaxf(vw, vhw));
    }
    __syncthreads();
    #pragma unroll
    for (int k = 0; k < 32; k += 8) {
        int hw = hw0 + threadIdx.y + k;
        if (hw < HW) {
            size_t o = obase + (size_t)hw * CHN + c0 + threadIdx.x;
            g_T00[o] = t00[threadIdx.x][threadIdx.y + k];
            g_TP [o] = tP [threadIdx.x][threadIdx.y + k];
            g_TQ [o] = tQ [threadIdx.x][threadIdx.y + k];
            g_TPQ[o] = tPQ[threadIdx.x][threadIdx.y + k];
        }
    }
}

__device__ __forceinline__ float4 max4(float4 a, float4 b)
{
    return make_float4(fmaxf(a.x, b.x), fmaxf(a.y, b.y),
                       fmaxf(a.z, b.z), fmaxf(a.w, b.w));
}

// ---------------------------------------------------------------------------
// Pass 2: grid = (NUM_ROIS, OUT_H), block = (C4, OUT_W) = (64, 7)
// ---------------------------------------------------------------------------
__global__ void __launch_bounds__(PTHREADS, 4)
roi_pool_pyr(float* __restrict__ out)
{
    __shared__ float s[CHN * OUT_W];      // s[c*7 + j]

    int roi  = blockIdx.x;
    int i    = blockIdx.y;
    int lane = threadIdx.x;               // c4 index
    int j    = threadIdx.y;               // warp-uniform

    int hb = g_hb[roi * OUT_H + i];
    int wb = g_wb[roi * OUT_W + j];
    int hs = hb & 0xff, he = hb >> 8, nh = he - hs;   // block-uniform
    int ws = wb & 0xff, we = wb >> 8, nw = we - ws;   // warp-uniform

    bool hp = (nh > 1), wp = (nw > 1);
    const float* tabf = hp ? (wp ? g_TPQ : g_TP)
                           : (wp ? g_TQ  : g_T00);
    const float4* tab = (const float4*)tabf + g_base4[roi] + lane;

    int hlast = hp ? (he - 2) : hs;
    int wlast = wp ? (we - 2) : ws;
    int KH = (nh + 1) >> 1;               // ceil(nh/2); ==1 when nh==1
    int KW = (nw + 1) >> 1;

    const float NI = -__int_as_float(0x7f800000);
    float4 m0 = make_float4(NI, NI, NI, NI);
    float4 m1 = m0;

    for (int kh = 0; kh < KH; ++kh) {
        int h = min(hs + 2 * kh, hlast);
        const float4* rp = tab + (size_t)(h * W_) * C4;
        for (int kw = 0; kw < KW; ++kw) {
            int w = min(ws + 2 * kw, wlast);
            float4 v = rp[(size_t)w * C4];
            if (kw & 1) m1 = max4(m1, v);
            else        m0 = max4(m0, v);
        }
    }
    float4 m = max4(m0, m1);

    // stage as s[c*7 + j]
    int c0 = lane * 4;
    s[(c0 + 0) * OUT_W + j] = m.x;
    s[(c0 + 1) * OUT_W + j] = m.y;
    s[(c0 + 2) * OUT_W + j] = m.z;
    s[(c0 + 3) * OUT_W + j] = m.w;
    __syncthreads();

    // out[roi][c][i*7 + jj]; linear smem read, one div-by-7 per thread
    int tid = threadIdx.y * C4 + threadIdx.x;     // 0..447
    int cq  = tid / OUT_W;
    int jr  = tid - cq * OUT_W;
    float* ob = out + (size_t)roi * CHN * BINS + i * OUT_W + jr;
    #pragma unroll
    for (int k = 0; k < 4; ++k)
        ob[(size_t)(cq + 64 * k) * BINS] = s[tid + k * PTHREADS];
}

extern "C" void kernel_launch(void* const* d_in, const int* in_sizes, int n_in,
                              void* d_out, int out_size)
{
    const float* feat = (const float*)d_in[0];
    const float* rois = (const float*)d_in[1];
    float* out = (float*)d_out;

    dim3 tgrid((HW + 31) / 32, CHN / 32, N_IMG);
    dim3 tblock(32, 8);
    build_kernel<<<tgrid, tblock>>>(feat, rois);

    dim3 pgrid(NUM_ROIS, OUT_H);
    dim3 pblock(C4, OUT_W);
    roi_pool_pyr<<<pgrid, pblock>>>(out);
}

// round 16
// speedup vs baseline: 1.7669x; 1.2872x over previous
#include <cuda_runtime.h>
#include <math.h>

// ROI max pooling via 2x2 max-pyramid tables + batched warp-uniform loads.
//
// Pass 1 (fused): NCHW [2,256,38,38] -> four NHWC tables [2,38,38,256]:
//   T00=feat, TP=max over {h,h+1}, TQ=max over {w,w+1}, TPQ=2x2 max (clamped).
//   Block (0,0,0) also precomputes per-roi bin bounds (packed ints).
//
// Pass 2: grid=(roi,i), block=(64 c4-lanes, 7 j)=448 threads; thread = one
//   bin x 4 channels. Bin [hs,he)x[ws,we) covered by KH x KW pyramid loads,
//   KH=ceil(nh/2)<=4, KW=ceil(nw/2)<=4, positions min(start+2k, end-2)
//   (overlap fine for max; n==1 dims use the non-paired table).
//   KW/KH are warp-uniform -> switch(KW) + if(KH==1) are uniform branches.
//   Each round's loads (<=4 float4) issue back-to-back BEFORE any consuming
//   max -> typical bin = ONE long-scoreboard stall round.
//
// Bin math (non-negative ints == Python floor-div):
//   x1=floor(rx1/16),..., rh=y2-y1+1, rw=x2-x1+1
//   hstart_i = y1 + (i*rh)/7, hend_i = y1 + ((i+1)*rh+6)/7  (same for w/j)
// Coords in [0,607.9] => windows inside [0,38), non-empty.

#define N_IMG 2
#define CHN   256
#define C4    (CHN/4)            // 64
#define H_    38
#define W_    38
#define HW    (H_ * W_)
#define NUM_ROIS 256
#define OUT_H 7
#define OUT_W 7
#define BINS  (OUT_H * OUT_W)
#define SPATIAL_SCALE 0.0625f
#define PTHREADS (C4 * OUT_W)    // 448
#define RSTRIDE ((size_t)(W_ * C4))   // row stride in float4 units

__device__ float g_T00[N_IMG * HW * CHN];   // [N][H][W][C]
__device__ float g_TP [N_IMG * HW * CHN];
__device__ float g_TQ [N_IMG * HW * CHN];
__device__ float g_TPQ[N_IMG * HW * CHN];
__device__ int   g_base4[NUM_ROIS];         // b * HW * C4 (float4 units)
__device__ int   g_hb[NUM_ROIS * OUT_H];    // hstart | hend<<8
__device__ int   g_wb[NUM_ROIS * OUT_W];    // wstart | wend<<8

// ---------------------------------------------------------------------------
// Pass 1: transpose + pyramid build + (block 0) bounds precompute.
// ---------------------------------------------------------------------------
__global__ void build_kernel(const float* __restrict__ in,
                             const float* __restrict__ rois)
{
    __shared__ float t00[32][33], tP[32][33], tQ[32][33], tPQ[32][33];
    int n   = blockIdx.z;
    int hw0 = blockIdx.x * 32;
    int c0  = blockIdx.y * 32;

    if (blockIdx.x == 0 && blockIdx.y == 0 && blockIdx.z == 0) {
        int t = threadIdx.y * 32 + threadIdx.x;     // 0..255
        if (t < NUM_ROIS) {
            const float* r = rois + t * 5;
            int b  = (int)r[0];
            int x1 = (int)floorf(r[1] * SPATIAL_SCALE);
            int y1 = (int)floorf(r[2] * SPATIAL_SCALE);
            int x2 = (int)floorf(r[3] * SPATIAL_SCALE);
            int y2 = (int)floorf(r[4] * SPATIAL_SCALE);
            int rh = y2 - y1 + 1;
            int rw = x2 - x1 + 1;
            g_base4[t] = b * HW * C4;
            #pragma unroll
            for (int i = 0; i < OUT_H; ++i) {
                int hs = y1 + (i * rh) / OUT_H;
                int he = y1 + ((i + 1) * rh + OUT_H - 1) / OUT_H;
                g_hb[t * OUT_H + i] = hs | (he << 8);
            }
            #pragma unroll
            for (int j = 0; j < OUT_W; ++j) {
                int ws = x1 + (j * rw) / OUT_W;
                int we = x1 + ((j + 1) * rw + OUT_W - 1) / OUT_W;
                g_wb[t * OUT_W + j] = ws | (we << 8);
            }
        }
    }

    const float* inp = in + (size_t)n * CHN * HW;
    size_t obase = (size_t)n * HW * CHN;

    #pragma unroll
    for (int k = 0; k < 32; k += 8) {
        int c  = c0 + threadIdx.y + k;
        int hw = hw0 + threadIdx.x;
        float v0 = 0.f, vh = 0.f, vw = 0.f, vhw = 0.f;
        if (hw < HW) {
            int h = hw / W_;
            int w = hw - h * W_;
            int dw = (w + 1 < W_) ? 1  : 0;
            int dh = (h + 1 < H_) ? W_ : 0;
            const float* p = inp + (size_t)c * HW + hw;
            v0  = p[0];
            vw  = p[dw];
            vh  = p[dh];
            vhw = p[dh + dw];
        }
        t00[threadIdx.y + k][threadIdx.x] = v0;
        tP [threadIdx.y + k][threadIdx.x] = fmaxf(v0, vh);
        tQ [threadIdx.y + k][threadIdx.x] = fmaxf(v0, vw);
        tPQ[threadIdx.y + k][threadIdx.x] = fmaxf(fmaxf(v0, vh), fmaxf(vw, vhw));
    }
    __syncthreads();
    #pragma unroll
    for (int k = 0; k < 32; k += 8) {
        int hw = hw0 + threadIdx.y + k;
        if (hw < HW) {
            size_t o = obase + (size_t)hw * CHN + c0 + threadIdx.x;
            g_T00[o] = t00[threadIdx.x][threadIdx.y + k];
            g_TP [o] = tP [threadIdx.x][threadIdx.y + k];
            g_TQ [o] = tQ [threadIdx.x][threadIdx.y + k];
            g_TPQ[o] = tPQ[threadIdx.x][threadIdx.y + k];
        }
    }
}

__device__ __forceinline__ float4 max4(float4 a, float4 b)
{
    return make_float4(fmaxf(a.x, b.x), fmaxf(a.y, b.y),
                       fmaxf(a.z, b.z), fmaxf(a.w, b.w));
}

// ---------------------------------------------------------------------------
// Pass 2: grid = (NUM_ROIS, OUT_H), block = (C4, OUT_W) = (64, 7)
// ---------------------------------------------------------------------------
__global__ void __launch_bounds__(PTHREADS, 4)
roi_pool_pyr(float* __restrict__ out)
{
    __shared__ float s[CHN * OUT_W];      // s[c*7 + j]

    int roi  = blockIdx.x;
    int i    = blockIdx.y;
    int lane = threadIdx.x;               // c4 index
    int j    = threadIdx.y;               // warp-uniform

    int hb = g_hb[roi * OUT_H + i];
    int wb = g_wb[roi * OUT_W + j];
    int hs = hb & 0xff, he = hb >> 8, nh = he - hs;   // block-uniform
    int ws = wb & 0xff, we = wb >> 8, nw = we - ws;   // warp-uniform

    bool hp = (nh > 1), wp = (nw > 1);
    const float* tabf = hp ? (wp ? g_TPQ : g_TP)
                           : (wp ? g_TQ  : g_T00);
    const float4* tab = (const float4*)tabf + g_base4[roi] + lane;

    int hlast = hp ? (he - 2) : hs;
    int wlast = wp ? (we - 2) : ws;
    int KH = (nh + 1) >> 1;               // 1..4, block-uniform
    int KW = (nw + 1) >> 1;               // 1..4, warp-uniform

    // column offsets (float4 units); clamped, duplicates harmless for max
    int w0 = ws * C4;
    int w1 = min(ws + 2, wlast) * C4;
    int w2 = min(ws + 4, wlast) * C4;
    int w3 = min(ws + 6, wlast) * C4;

    const float NI = -__int_as_float(0x7f800000);
    float4 m0 = make_float4(NI, NI, NI, NI);
    float4 m1 = m0;

    const float4* r0 = tab + (size_t)hs * RSTRIDE;

    switch (KW) {
    case 1:
        if (KH == 1) {
            m0 = r0[w0];
        } else {
            for (int kh = 0; kh < KH; kh += 2) {
                const float4* ra = tab + (size_t)min(hs + 2*kh,     hlast) * RSTRIDE;
                const float4* rb = tab + (size_t)min(hs + 2*kh + 2, hlast) * RSTRIDE;
                float4 a = ra[w0];
                float4 b = rb[w0];
                m0 = max4(m0, a);
                m1 = max4(m1, b);
            }
        }
        break;
    case 2:
        if (KH == 1) {
            float4 a = r0[w0];
            float4 b = r0[w1];
            m0 = a; m1 = b;
        } else {
            for (int kh = 0; kh < KH; kh += 2) {
                const float4* ra = tab + (size_t)min(hs + 2*kh,     hlast) * RSTRIDE;
                const float4* rb = tab + (size_t)min(hs + 2*kh + 2, hlast) * RSTRIDE;
                float4 a = ra[w0];
                float4 b = ra[w1];
                float4 c = rb[w0];
                float4 d = rb[w1];
                m0 = max4(m0, max4(a, c));
                m1 = max4(m1, max4(b, d));
            }
        }
        break;
    case 3:
        for (int kh = 0; kh < KH; ++kh) {
            const float4* rp = tab + (size_t)min(hs + 2*kh, hlast) * RSTRIDE;
            float4 a = rp[w0];
            float4 b = rp[w1];
            float4 c = rp[w2];
            m0 = max4(m0, max4(a, b));
            m1 = max4(m1, c);
        }
        break;
    default:  // KW == 4
        for (int kh = 0; kh < KH; ++kh) {
            const float4* rp = tab + (size_t)min(hs + 2*kh, hlast) * RSTRIDE;
            float4 a = rp[w0];
            float4 b = rp[w1];
            float4 c = rp[w2];
            float4 d = rp[w3];
            m0 = max4(m0, max4(a, b));
            m1 = max4(m1, max4(c, d));
        }
        break;
    }
    float4 m = max4(m0, m1);

    // stage as s[c*7 + j]
    int c0 = lane * 4;
    s[(c0 + 0) * OUT_W + j] = m.x;
    s[(c0 + 1) * OUT_W + j] = m.y;
    s[(c0 + 2) * OUT_W + j] = m.z;
    s[(c0 + 3) * OUT_W + j] = m.w;
    __syncthreads();

    // out[roi][c][i*7 + jj]; linear smem read, one div-by-7 per thread
    int tid = threadIdx.y * C4 + threadIdx.x;     // 0..447
    int cq  = tid / OUT_W;
    int jr  = tid - cq * OUT_W;
    float* ob = out + (size_t)roi * CHN * BINS + i * OUT_W + jr;
    #pragma unroll
    for (int k = 0; k < 4; ++k)
        ob[(size_t)(cq + 64 * k) * BINS] = s[tid + k * PTHREADS];
}

extern "C" void kernel_launch(void* const* d_in, const int* in_sizes, int n_in,
                              void* d_out, int out_size)
{
    const float* feat = (const float*)d_in[0];
    const float* rois = (const float*)d_in[1];
    float* out = (float*)d_out;

    dim3 tgrid((HW + 31) / 32, CHN / 32, N_IMG);
    dim3 tblock(32, 8);
    build_kernel<<<tgrid, tblock>>>(feat, rois);

    dim3 pgrid(NUM_ROIS, OUT_H);
    dim3 pblock(C4, OUT_W);
    roi_pool_pyr<<<pgrid, pblock>>>(out);
}